// round 1
// baseline (speedup 1.0000x reference)
#include <cuda_runtime.h>

// ---------------------------------------------------------------------------
// CustomLSTM: B=2048, T=256, I=5, H=50, O=1
//
// Design: 128 blocks x 200 threads. Each block owns NB=16 batch elements for
// the whole sequence (no global sync; recurrence dependency is block-local).
// Two batches are packed per lane as f32x2 and processed with fma.rn.f32x2
// (FFMA2, 2x fp32 throughput). Each thread permanently owns one of the 200
// gate rows with its Wh(50)+Wx(5) weights pre-packed in registers, so the
// inner loop reads only broadcast LDS of the shared h-state. Gate results are
// exchanged via a conflict-free shared buffer; c-state stays in registers of
// the fixed updater thread. x is staged in shared once (80KB) so the
// steady-state loop does zero global traffic.
// ---------------------------------------------------------------------------

typedef unsigned long long ull;

constexpr int B  = 2048;
constexpr int T  = 256;
constexpr int I  = 5;
constexpr int H  = 50;
constexpr int G  = 4 * H;   // 200 gates
constexpr int NB = 16;      // batches per block
constexpr int NP = NB / 2;  // f32x2 pairs per block = 8
constexpr int NTH = 200;    // one thread per gate row
constexpr int NBLK = B / NB; // 128

constexpr int XS_ULL = NP * T * I;   // 10240  x staging  [p][t][i]
constexpr int GB_ULL = NP * G;       // 1600   gate buf   [p][g]
constexpr int HS_ULL = NP * H;       // 400    h state    [p][k]
constexpr size_t SMEM_BYTES = (size_t)(XS_ULL + GB_ULL + HS_ULL) * 8; // 97920

__device__ __forceinline__ ull fma2(ull a, ull b, ull c) {
    ull d;
    asm("fma.rn.f32x2 %0, %1, %2, %3;" : "=l"(d) : "l"(a), "l"(b), "l"(c));
    return d;
}
__device__ __forceinline__ ull pack2(float x, float y) {
    ull r;
    asm("mov.b64 %0, {%1, %2};" : "=l"(r) : "f"(x), "f"(y));
    return r;
}
__device__ __forceinline__ float2 unpack2(ull v) {
    float2 r;
    asm("mov.b64 {%0, %1}, %2;" : "=f"(r.x), "=f"(r.y) : "l"(v));
    return r;
}
__device__ __forceinline__ float sigf(float x) {
    return __fdividef(1.0f, 1.0f + __expf(-x));
}
__device__ __forceinline__ float tanh_fast(float x) {
    float a = fabsf(x);
    float e = __expf(-2.0f * a);
    float t = __fdividef(1.0f - e, 1.0f + e);
    return copysignf(t, x);
}

__global__ void __launch_bounds__(NTH, 1) lstm_fused_kernel(
    const float* __restrict__ x,
    const float* __restrict__ Wxf, const float* __restrict__ bxf,
    const float* __restrict__ Wxi, const float* __restrict__ bxi,
    const float* __restrict__ Wxc, const float* __restrict__ bxc,
    const float* __restrict__ Wxo, const float* __restrict__ bxo,
    const float* __restrict__ Whf, const float* __restrict__ bhf,
    const float* __restrict__ Whi, const float* __restrict__ bhi,
    const float* __restrict__ Whc, const float* __restrict__ bhc,
    const float* __restrict__ Who, const float* __restrict__ bho,
    const float* __restrict__ bf,  const float* __restrict__ bi,
    const float* __restrict__ bc,  const float* __restrict__ bo,
    const float* __restrict__ Wfc, const float* __restrict__ bfc,
    float* __restrict__ out)
{
    extern __shared__ ull sm[];
    ull* xs = sm;                       // [NP][T][I]
    ull* gb = sm + XS_ULL;              // [NP][G]
    ull* hs = sm + XS_ULL + GB_ULL;     // [NP][H]

    const int tid = threadIdx.x;
    const int b0  = blockIdx.x * NB;

    // ---- stage x for this block's 16 batches into shared (interleaved pairs)
    {
        float* xsf = (float*)xs;
        for (int idx = tid; idx < NB * T * I; idx += NTH) {
            int lb = idx / (T * I);
            int r  = idx - lb * (T * I);
            xsf[((lb >> 1) * (T * I) + r) * 2 + (lb & 1)] =
                x[(size_t)(b0 + lb) * (T * I) + r];
        }
    }
    // ---- zero h state
    for (int idx = tid; idx < HS_ULL; idx += NTH) hs[idx] = 0ull;

    // ---- load this thread's gate-row weights into registers (packed f32x2)
    const int g  = tid;          // 0..199
    const int q  = g / H;        // gate: 0=f 1=i 2=c 3=o
    const int jj = g - q * H;    // hidden unit within gate
    const float* whp;
    const float* wxp;
    float btot;
    if (q == 0)      { whp = Whf + jj * H; wxp = Wxf + jj * I; btot = bxf[jj] + bhf[jj] + bf[jj]; }
    else if (q == 1) { whp = Whi + jj * H; wxp = Wxi + jj * I; btot = bxi[jj] + bhi[jj] + bi[jj]; }
    else if (q == 2) { whp = Whc + jj * H; wxp = Wxc + jj * I; btot = bxc[jj] + bhc[jj] + bc[jj]; }
    else             { whp = Who + jj * H; wxp = Wxo + jj * I; btot = bxo[jj] + bho[jj] + bo[jj]; }

    ull w2[H];
#pragma unroll
    for (int k = 0; k < H; k++) { float w = whp[k]; w2[k] = pack2(w, w); }
    ull wx2[I];
#pragma unroll
    for (int i = 0; i < I; i++) { float w = wxp[i]; wx2[i] = pack2(w, w); }
    const ull bias2 = pack2(btot, btot);

    // ---- fixed update-phase mapping: thread handles 2 (unit j, pair p) items
    const int j0 = tid % H, p0 = tid / H;           // p0 in 0..3
    const int j1 = (tid + NTH) % H, p1 = (tid + NTH) / H; // p1 in 4..7
    float2 c0 = make_float2(0.0f, 0.0f);
    float2 c1 = make_float2(0.0f, 0.0f);

    __syncthreads();

    // =============================== time loop ==============================
    for (int t = 0; t < T; t++) {
        // ---- phase A: this thread's gate for all 8 batch-pairs
        ull acc[NP];
#pragma unroll
        for (int p = 0; p < NP; p++) acc[p] = bias2;

#pragma unroll
        for (int k = 0; k < H; k += 2) {
#pragma unroll
            for (int p = 0; p < NP; p++) {
                // broadcast LDS.128: (h[k], h[k+1]) for pair p
                ulonglong2 hv = *(const ulonglong2*)(hs + p * H + k);
                acc[p] = fma2(hv.x, w2[k],     acc[p]);
                acc[p] = fma2(hv.y, w2[k + 1], acc[p]);
            }
        }
#pragma unroll
        for (int i = 0; i < I; i++) {
#pragma unroll
            for (int p = 0; p < NP; p++) {
                acc[p] = fma2(xs[(p * T + t) * I + i], wx2[i], acc[p]);
            }
        }
#pragma unroll
        for (int p = 0; p < NP; p++) gb[p * G + g] = acc[p];
        __syncthreads();

        // ---- phase B: gate nonlinearity + state update (2 items per thread)
        {
            float2 gf = unpack2(gb[p0 * G + j0]);
            float2 gi = unpack2(gb[p0 * G + H + j0]);
            float2 gc = unpack2(gb[p0 * G + 2 * H + j0]);
            float2 go = unpack2(gb[p0 * G + 3 * H + j0]);
            c0.x = sigf(gf.x) * c0.x + sigf(gi.x) * tanh_fast(gc.x);
            c0.y = sigf(gf.y) * c0.y + sigf(gi.y) * tanh_fast(gc.y);
            float hx = sigf(go.x) * tanh_fast(c0.x);
            float hy = sigf(go.y) * tanh_fast(c0.y);
            hs[p0 * H + j0] = pack2(hx, hy);
        }
        {
            float2 gf = unpack2(gb[p1 * G + j1]);
            float2 gi = unpack2(gb[p1 * G + H + j1]);
            float2 gc = unpack2(gb[p1 * G + 2 * H + j1]);
            float2 go = unpack2(gb[p1 * G + 3 * H + j1]);
            c1.x = sigf(gf.x) * c1.x + sigf(gi.x) * tanh_fast(gc.x);
            c1.y = sigf(gf.y) * c1.y + sigf(gi.y) * tanh_fast(gc.y);
            float hx = sigf(go.x) * tanh_fast(c1.x);
            float hy = sigf(go.y) * tanh_fast(c1.y);
            hs[p1 * H + j1] = pack2(hx, hy);
        }
        __syncthreads();
    }

    // ---- final projection: out[b] = h_T[b] . Wfc + bfc   (O = 1)
    if (tid < NB) {
        const int p = tid >> 1, half = tid & 1;
        const float* hsf = (const float*)hs;
        float s = bfc[0];
#pragma unroll
        for (int k = 0; k < H; k++) {
            s += hsf[(p * H + k) * 2 + half] * Wfc[k];
        }
        out[b0 + tid] = s;
    }
}

extern "C" void kernel_launch(void* const* d_in, const int* in_sizes, int n_in,
                              void* d_out, int out_size)
{
    (void)in_sizes; (void)n_in; (void)out_size;
    const float* x   = (const float*)d_in[0];
    const float* Wxf = (const float*)d_in[1];
    const float* bxf = (const float*)d_in[2];
    const float* Wxi = (const float*)d_in[3];
    const float* bxi = (const float*)d_in[4];
    const float* Wxc = (const float*)d_in[5];
    const float* bxc = (const float*)d_in[6];
    const float* Wxo = (const float*)d_in[7];
    const float* bxo = (const float*)d_in[8];
    const float* Whf = (const float*)d_in[9];
    const float* bhf = (const float*)d_in[10];
    const float* Whi = (const float*)d_in[11];
    const float* bhi = (const float*)d_in[12];
    const float* Whc = (const float*)d_in[13];
    const float* bhc = (const float*)d_in[14];
    const float* Who = (const float*)d_in[15];
    const float* bho = (const float*)d_in[16];
    const float* bf  = (const float*)d_in[17];
    const float* bi  = (const float*)d_in[18];
    const float* bc  = (const float*)d_in[19];
    const float* bo  = (const float*)d_in[20];
    const float* Wfc = (const float*)d_in[21];
    const float* bfc = (const float*)d_in[22];
    float* out = (float*)d_out;

    cudaFuncSetAttribute(lstm_fused_kernel,
                         cudaFuncAttributeMaxDynamicSharedMemorySize,
                         (int)SMEM_BYTES);

    lstm_fused_kernel<<<NBLK, NTH, SMEM_BYTES>>>(
        x,
        Wxf, bxf, Wxi, bxi, Wxc, bxc, Wxo, bxo,
        Whf, bhf, Whi, bhi, Whc, bhc, Who, bho,
        bf, bi, bc, bo,
        Wfc, bfc,
        out);
}